// round 16
// baseline (speedup 1.0000x reference)
#include <cuda_runtime.h>
#include <cstdint>

static constexpr int   T_LEN = 4096;
static constexpr int   TC    = 64;            // steps per chunk
static constexpr int   NCH   = T_LEN / TC;    // 64
static constexpr int   R64   = 64;            // rows per block (2 chains/lane in w0)
static constexpr int   XD    = 6;             // x ring: spans k-3 .. k+2
static constexpr int   VD    = 2;             // v / s buffer ring depth
static constexpr int   SD    = 4;             // spike-bit ring: spans k-3 .. k
static constexpr int   STRW  = 68;            // padded words/row (bank-safe)
static constexpr float VTH   = 1.27f;
static constexpr int   DVSPLIT = 9;           // dv store: w2 does r<9, w3 does r>=9

static constexpr int XT_SZ = XD * R64 * STRW;
static constexpr int VB_SZ = VD * R64 * STRW;
static constexpr int SS_SZ = VD * R64 * STRW;
static constexpr int SB_SZ = SD * R64 * 2;
static constexpr int WR_SZ = 2 * R64 * 2;
static constexpr size_t SMEM_BYTES =
    (size_t)(XT_SZ + VB_SZ + SS_SZ + SB_SZ + WR_SZ) * 4;

// Coalesced chunk copy-issue for 64 rows: lane (q2=lane>>4, m2=lane&15) covers
// row 2r+q2, bytes 16*m2, r=0..31. Caller commits (possibly empty) groups so
// wait_group depth accounting stays exact on the tail (round-8 invariant).
__device__ __forceinline__ void cp_chunk_issue(const float* gchunk, float* stile,
                                               int q2, int m2)
{
#pragma unroll 8
    for (int r = 0; r < 32; ++r) {
        const int rr = 2 * r + q2;
        unsigned sa = (unsigned)__cvta_generic_to_shared(stile + rr * STRW + 4 * m2);
        asm volatile("cp.async.ca.shared.global [%0], [%1], 16;\n"
                     :: "r"(sa), "l"(gchunk + (size_t)rr * T_LEN + 4 * m2));
    }
}

__device__ __forceinline__ void cp_commit()
{
    asm volatile("cp.async.commit_group;\n");
}

// dv store for rows 2r+q2, r in [r0, r1): dv = x & ~window_mask
__device__ __forceinline__ void dv_store_rows(
    const float* xb, const unsigned* Wslot, float* dout,
    int r0, int r1, int q2, int m2)
{
    const int h  = m2 >> 3;
    const int tb = 4 * (m2 & 7);
#pragma unroll 4
    for (int r = r0; r < r1; ++r) {
        const int rr = 2 * r + q2;
        const unsigned V = Wslot[rr * 2 + h];
        float4 x4 = *reinterpret_cast<const float4*>(xb + rr * STRW + 4 * m2);
        int xw[4] = {__float_as_int(x4.x), __float_as_int(x4.y),
                     __float_as_int(x4.z), __float_as_int(x4.w)};
        float rv[4];
#pragma unroll
        for (int j = 0; j < 4; ++j) {
            int mskb = (int)(V << (31 - (tb + j))) >> 31;  // ~0 iff zeroed
            rv[j] = __int_as_float(xw[j] & ~mskb);
        }
        *reinterpret_cast<float4*>(dout + (size_t)rr * T_LEN + 4 * m2) =
            make_float4(rv[0], rv[1], rv[2], rv[3]);
    }
}

__global__ void __launch_bounds__(128)
lif_fused(const float* __restrict__ ode, const float* __restrict__ decay_p,
          float* __restrict__ v_out, float* __restrict__ s_out,
          float* __restrict__ dv_out)
{
    extern __shared__ float smf[];
    float*    xt = smf;                       // [XD][R64][STRW] input chunks
    float*    vb = xt + XT_SZ;                // [VD][R64][STRW] clamped v
    float*    ssb = vb + VB_SZ;               // [VD][R64][STRW] s floats
    unsigned* sb = (unsigned*)(ssb + SS_SZ);  // [SD][R64][2] spike bits
    unsigned* Wr = sb + SB_SZ;                // [2][R64][2] dv window ring

    const int wid  = threadIdx.x >> 5;
    const int lane = threadIdx.x & 31;
    const int q2   = lane >> 4;               // 0..1 : row parity group
    const int m2   = lane & 15;               // 0..15: 16B segment in chunk
    const int row0 = blockIdx.x * R64;
    const float dec = __ldg(decay_p);
    const float* xg0 = ode + (size_t)row0 * T_LEN;

    // w0 scan state, two independent chains per lane (rows lane, lane+32):
    // aa = masked pre-clamp value of previous step,
    // s1..s5 = spike masks (~0 iff spike) for steps t-1..t-5.
    float aa[2] = {0.0f, 0.0f};
    int s1[2] = {0, 0}, s2[2] = {0, 0}, s3[2] = {0, 0},
        s4[2] = {0, 0}, s5[2] = {0, 0};

    if (wid == 1) {
        cp_chunk_issue(xg0 + 0 * TC, xt + 0 * R64 * STRW, q2, m2); cp_commit();
        cp_chunk_issue(xg0 + 1 * TC, xt + 1 * R64 * STRW, q2, m2); cp_commit();
        asm volatile("cp.async.wait_group 1;\n" ::: "memory");  // chunk 0 ready
    }
    __syncthreads();

    for (int k = 0; k < NCH + 3; ++k) {
        // ---------------- w0: scan chunk k, 2 chains ----------------
        if (wid == 0 && k < NCH) {
            const float* xrb = xt + (k % XD) * R64 * STRW + lane * STRW;
            float*       vrb = vb + (k % VD) * R64 * STRW + lane * STRW;
            float*       srb = ssb + (k % VD) * R64 * STRW + lane * STRW;
            unsigned b0[2] = {0u, 0u}, b1[2] = {0u, 0u};
            if (k == 0) {
                // general machine per chain (t=0 edge exact)
#pragma unroll
                for (int ch = 0; ch < 2; ++ch) {
                    const float* xr = xrb + 32 * ch * STRW;
                    float* vr = vrb + 32 * ch * STRW;
                    float* sr = srb + 32 * ch * STRW;
                    float v = 0.0f, t2 = 0.0f; int c = 0, z = 0; bool s = false;
                    unsigned bits0 = 0u, bits1 = 0u;
#pragma unroll 4
                    for (int t = 0; t < TC; ++t) {
                        float x  = xr[t];
                        float xe = (z > 0) ? 0.0f : x;
                        float vd = fmaf(-dec, v, v);
                        float a  = vd + xe;
                        float b  = (c == 1) ? xe : a;
                        t2 = (c >= 2) ? VTH : b;
                        s  = t2 > VTH;
                        v  = fminf(t2, VTH);
                        vr[t] = v;
                        sr[t] = s ? 1.0f : 0.0f;
                        if (t < 32) bits0 |= s ? (1u << t) : 0u;
                        else        bits1 |= s ? (1u << (t - 32)) : 0u;
                        c = s ? (c + 1) : (c > 0 ? c - 1 : 0);
                        z = s ? (t > 0 ? 5 : z) : (z > 0 ? z - 1 : 0);
                    }
                    aa[ch] = t2;
                    s1[ch] = (int)bits1 >> 31;
                    s2[ch] = (int)(bits1 << 1) >> 31;
                    s3[ch] = (int)(bits1 << 2) >> 31;
                    s4[ch] = (int)(bits1 << 3) >> 31;
                    s5[ch] = (int)(bits1 << 4) >> 31;
                    b0[ch] = bits0; b1[ch] = bits1;
                }
            } else {
                float4 xc[2], xn[2];
                xc[0] = *reinterpret_cast<const float4*>(xrb);
                xc[1] = *reinterpret_cast<const float4*>(xrb + 32 * STRW);
#pragma unroll
                for (int g4 = 0; g4 < 16; ++g4) {
                    if (g4 < 15) {
                        xn[0] = *reinterpret_cast<const float4*>(xrb + 4 * (g4 + 1));
                        xn[1] = *reinterpret_cast<const float4*>(xrb + 32 * STRW + 4 * (g4 + 1));
                    }
                    float xs[2][4] = {{xc[0].x, xc[0].y, xc[0].z, xc[0].w},
                                      {xc[1].x, xc[1].y, xc[1].z, xc[1].w}};
                    float vs[2][4], sf[2][4];
#pragma unroll
                    for (int qq = 0; qq < 4; ++qq) {
                        const int t = 4 * g4 + qq;
#pragma unroll
                        for (int ch = 0; ch < 2; ++ch) {
                            int wm = s2[ch] | s3[ch] | s4[ch];
                            int xm = __float_as_int(xs[ch][qq]) & ~wm & ~s5[ch];
                            float vd  = fmaf(-dec, aa[ch], aa[ch]);
                            float sum = vd + __int_as_float(xm);
                            float aan = __int_as_float(__float_as_int(sum) & ~s1[ch]);
                            int   sm  = __float_as_int(VTH - aan) >> 31;
                            vs[ch][qq] = fminf(aan, VTH);
                            sf[ch][qq] = __int_as_float(sm & 0x3f800000);
                            if (t < 32) b0[ch] |= (1u << t) & (unsigned)sm;
                            else        b1[ch] |= (1u << (t - 32)) & (unsigned)sm;
                            s5[ch] = s4[ch]; s4[ch] = s3[ch]; s3[ch] = s2[ch];
                            s2[ch] = s1[ch]; s1[ch] = sm;
                            aa[ch] = aan;
                        }
                    }
#pragma unroll
                    for (int ch = 0; ch < 2; ++ch) {
                        *reinterpret_cast<float4*>(vrb + 32 * ch * STRW + 4 * g4) =
                            make_float4(vs[ch][0], vs[ch][1], vs[ch][2], vs[ch][3]);
                        *reinterpret_cast<float4*>(srb + 32 * ch * STRW + 4 * g4) =
                            make_float4(sf[ch][0], sf[ch][1], sf[ch][2], sf[ch][3]);
                    }
                    xc[0] = xn[0]; xc[1] = xn[1];
                }
            }
            unsigned* sbw = sb + (k % SD) * R64 * 2;
            sbw[lane * 2 + 0] = b0[0];
            sbw[lane * 2 + 1] = b1[0];
            sbw[(lane + 32) * 2 + 0] = b0[1];
            sbw[(lane + 32) * 2 + 1] = b1[1];
        }

        // ------ w1: prefetch + coalesced v store (chunk k-1) ------
        if (wid == 1) {
            if (k + 2 < NCH)
                cp_chunk_issue(xg0 + (size_t)(k + 2) * TC,
                               xt + ((k + 2) % XD) * R64 * STRW, q2, m2);
            cp_commit();   // ALWAYS commit (empty on tail): wait_group depth
                           // stays exact so chunk k+1 is provably complete
            const int c = k - 1;
            if (c >= 0 && c < NCH) {
                const float* vbb = vb + (c % VD) * R64 * STRW;
                float* vout = v_out + (size_t)row0 * T_LEN + (size_t)c * TC;
#pragma unroll 4
                for (int r = 0; r < 32; ++r) {
                    const int rr = 2 * r + q2;
                    float4 v4 = *reinterpret_cast<const float4*>(vbb + rr * STRW + 4 * m2);
                    *reinterpret_cast<float4*>(vout + (size_t)rr * T_LEN + 4 * m2) = v4;
                }
            }
            asm volatile("cp.async.wait_group 1;\n" ::: "memory");
        }

        // ------ w2: s copy (k-1) + dv window masks (k-2) + dv share (k-3) ------
        if (wid == 2) {
            const int c = k - 1;
            if (c >= 0 && c < NCH) {
                const float* sbbuf = ssb + (c % VD) * R64 * STRW;
                float* sout = s_out + (size_t)row0 * T_LEN + (size_t)c * TC;
#pragma unroll 4
                for (int r = 0; r < 32; ++r) {
                    const int rr = 2 * r + q2;
                    float4 s4v = *reinterpret_cast<const float4*>(sbbuf + rr * STRW + 4 * m2);
                    *reinterpret_cast<float4*>(sout + (size_t)rr * T_LEN + 4 * m2) = s4v;
                }
            }
            const int ca = k - 2;
            if (ca >= 0 && ca < NCH) {
                unsigned* Wdst = Wr + (k & 1) * R64 * 2;
#pragma unroll
                for (int cc = 0; cc < 2; ++cc) {
                    const int rw = lane + 32 * cc;
                    const unsigned* sbc = sb + (ca % SD) * R64 * 2 + rw * 2;
#pragma unroll
                    for (int h = 0; h < 2; ++h) {
                        unsigned mm, mp, mn;
                        if (h == 0) {
                            mm = sbc[0];
                            mp = (ca > 0) ? sb[((ca - 1) % SD) * R64 * 2 + rw * 2 + 1] : 0u;
                            mn = sbc[1] & 1u;
                            if (ca == 0) mm &= ~1u;  // spike at t=0 zeroes nothing
                        } else {
                            mm = sbc[1];
                            mp = sbc[0];
                            if (ca == 0) mp &= ~1u;
                            mn = (ca + 1 < NCH)
                                 ? (sb[((ca + 1) % SD) * R64 * 2 + rw * 2 + 0] & 1u) : 0u;
                        }
                        unsigned long long W = ((unsigned long long)mm << 5) | (mp >> 27)
                                             | ((unsigned long long)mn << 37);
                        W |= W >> 1; W |= W >> 2; W |= W >> 3;
                        Wdst[rw * 2 + h] = (unsigned)W;
                    }
                }
            }
            const int cd = k - 3;
            if (cd >= 0 && cd < NCH) {
                dv_store_rows(xt + (cd % XD) * R64 * STRW,
                              Wr + ((k - 1) & 1) * R64 * 2,
                              dv_out + (size_t)row0 * T_LEN + (size_t)cd * TC,
                              0, DVSPLIT, q2, m2);
            }
        }

        // ------ w3: dv store remainder (chunk k-3) ------
        if (wid == 3) {
            const int cd = k - 3;
            if (cd >= 0 && cd < NCH) {
                dv_store_rows(xt + (cd % XD) * R64 * STRW,
                              Wr + ((k - 1) & 1) * R64 * 2,
                              dv_out + (size_t)row0 * T_LEN + (size_t)cd * TC,
                              DVSPLIT, 32, q2, m2);
            }
        }

        __syncthreads();
    }
}

extern "C" void kernel_launch(void* const* d_in, const int* in_sizes, int n_in,
                              void* d_out, int out_size)
{
    const float* ode     = (const float*)d_in[0];
    const float* decay_p = (const float*)d_in[1];
    float*       out     = (float*)d_out;

    const int BT = in_sizes[0];
    const int B  = BT / T_LEN;

    float* v_out  = out;
    float* s_out  = out + (size_t)BT;
    float* dv_out = out + (size_t)2 * BT;

    cudaFuncSetAttribute(lif_fused, cudaFuncAttributeMaxDynamicSharedMemorySize,
                         (int)SMEM_BYTES);
    lif_fused<<<B / R64, 128, SMEM_BYTES>>>(ode, decay_p, v_out, s_out, dv_out);
}

// round 17
// speedup vs baseline: 1.0358x; 1.0358x over previous
#include <cuda_runtime.h>
#include <cstdint>

static constexpr int   T_LEN = 4096;
static constexpr int   TC    = 64;            // steps per chunk
static constexpr int   NCH   = T_LEN / TC;    // 64
static constexpr int   R64   = 64;            // rows per block (2 chains/lane in w0)
static constexpr int   XD    = 6;             // x ring: spans k-3 .. k+2
static constexpr int   VD    = 2;             // v / s buffer ring depth
static constexpr int   SD    = 4;             // spike-bit ring: spans k-3 .. k
static constexpr int   STRW  = 68;            // padded words/row (bank-safe)
static constexpr float VTH   = 1.27f;
static constexpr int   DVSPLIT = 9;           // dv store: w2 does r<9, w3 r>=9

static constexpr int XT_SZ = XD * R64 * STRW;
static constexpr int VB_SZ = VD * R64 * STRW;
static constexpr int SS_SZ = VD * R64 * STRW;
static constexpr int SB_SZ = SD * R64 * 2;
static constexpr int WR_SZ = 2 * R64 * 2;
static constexpr size_t SMEM_BYTES =
    (size_t)(XT_SZ + VB_SZ + SS_SZ + SB_SZ + WR_SZ) * 4;

// ---------------- scan-chain machinery (all scalar state) ----------------

struct Chain {
    float aa;                       // masked pre-clamp value of previous step
    int s1, s2, s3, s4, s5;         // spike masks (~0 iff spike) t-1..t-5
};

// One LIF step. Returns clamped v; writes s float and spike bit.
__device__ __forceinline__ float lif_step(Chain& c, float x, float dec,
                                          float& sf, unsigned& bits,
                                          unsigned bitpos)
{
    int   wm  = c.s2 | c.s3 | c.s4;
    int   xm  = __float_as_int(x) & ~wm & ~c.s5;          // window t-5..t-2
    float vd  = fmaf(-dec, c.aa, c.aa);
    float sum = vd + __int_as_float(xm);
    float aan = __int_as_float(__float_as_int(sum) & ~c.s1);  // reset (t-1)
    int   sm  = __float_as_int(VTH - aan) >> 31;          // ~0 iff spike
    float v   = fminf(aan, VTH);
    sf = __int_as_float(sm & 0x3f800000);
    bits |= bitpos & (unsigned)sm;
    c.s5 = c.s4; c.s4 = c.s3; c.s3 = c.s2; c.s2 = c.s1; c.s1 = sm;
    c.aa = aan;
    return v;
}

// General machine for chunk 0 (t=0 edge exact); hands off scalar chain state.
__device__ __forceinline__ void general_chunk(Chain& cc, const float* xr,
                                              float* vr, float* sr,
                                              unsigned& b0, unsigned& b1,
                                              float dec)
{
    float v = 0.0f, t2 = 0.0f; int c = 0, z = 0; bool s = false;
    unsigned bits0 = 0u, bits1 = 0u;
#pragma unroll 4
    for (int t = 0; t < TC; ++t) {
        float x  = xr[t];
        float xe = (z > 0) ? 0.0f : x;
        float vd = fmaf(-dec, v, v);
        float a  = vd + xe;
        float b  = (c == 1) ? xe : a;
        t2 = (c >= 2) ? VTH : b;
        s  = t2 > VTH;
        v  = fminf(t2, VTH);
        vr[t] = v;
        sr[t] = s ? 1.0f : 0.0f;
        if (t < 32) bits0 |= s ? (1u << t) : 0u;
        else        bits1 |= s ? (1u << (t - 32)) : 0u;
        c = s ? (c + 1) : (c > 0 ? c - 1 : 0);
        z = s ? (t > 0 ? 5 : z) : (z > 0 ? z - 1 : 0);
    }
    cc.aa = t2;
    cc.s1 = (int)bits1 >> 31;
    cc.s2 = (int)(bits1 << 1) >> 31;
    cc.s3 = (int)(bits1 << 2) >> 31;
    cc.s4 = (int)(bits1 << 3) >> 31;
    cc.s5 = (int)(bits1 << 4) >> 31;
    b0 = bits0; b1 = bits1;
}

// ---------------- coalesced global <-> shared helpers ----------------

// lane (q2=lane>>4, m2=lane&15) covers row 2r+q2, bytes 16*m2, r=0..31.
// Caller commits (possibly empty) groups so wait_group depth accounting
// stays exact on the tail (round-8 invariant).
__device__ __forceinline__ void cp_chunk_issue(const float* gchunk, float* stile,
                                               int q2, int m2)
{
#pragma unroll 8
    for (int r = 0; r < 32; ++r) {
        const int rr = 2 * r + q2;
        unsigned sa = (unsigned)__cvta_generic_to_shared(stile + rr * STRW + 4 * m2);
        asm volatile("cp.async.ca.shared.global [%0], [%1], 16;\n"
                     :: "r"(sa), "l"(gchunk + (size_t)rr * T_LEN + 4 * m2));
    }
}

__device__ __forceinline__ void cp_commit()
{
    asm volatile("cp.async.commit_group;\n");
}

// dv store for rows 2r+q2, r in [r0, r1): dv = x & ~window_mask
__device__ __forceinline__ void dv_store_rows(
    const float* xb, const unsigned* Wslot, float* dout,
    int r0, int r1, int q2, int m2)
{
    const int h  = m2 >> 3;
    const int tb = 4 * (m2 & 7);
#pragma unroll 4
    for (int r = r0; r < r1; ++r) {
        const int rr = 2 * r + q2;
        const unsigned V = Wslot[rr * 2 + h];
        float4 x4 = *reinterpret_cast<const float4*>(xb + rr * STRW + 4 * m2);
        int xw[4] = {__float_as_int(x4.x), __float_as_int(x4.y),
                     __float_as_int(x4.z), __float_as_int(x4.w)};
        float rv[4];
#pragma unroll
        for (int j = 0; j < 4; ++j) {
            int mskb = (int)(V << (31 - (tb + j))) >> 31;  // ~0 iff zeroed
            rv[j] = __int_as_float(xw[j] & ~mskb);
        }
        *reinterpret_cast<float4*>(dout + (size_t)rr * T_LEN + 4 * m2) =
            make_float4(rv[0], rv[1], rv[2], rv[3]);
    }
}

__global__ void __launch_bounds__(128)
lif_fused(const float* __restrict__ ode, const float* __restrict__ decay_p,
          float* __restrict__ v_out, float* __restrict__ s_out,
          float* __restrict__ dv_out)
{
    extern __shared__ float smf[];
    float*    xt  = smf;                      // [XD][R64][STRW] input chunks
    float*    vb  = xt + XT_SZ;               // [VD][R64][STRW] clamped v
    float*    ssb = vb + VB_SZ;               // [VD][R64][STRW] s floats
    unsigned* sb  = (unsigned*)(ssb + SS_SZ); // [SD][R64][2] spike bits
    unsigned* Wr  = sb + SB_SZ;               // [2][R64][2] dv window ring

    const int wid  = threadIdx.x >> 5;
    const int lane = threadIdx.x & 31;
    const int q2   = lane >> 4;
    const int m2   = lane & 15;
    const int row0 = blockIdx.x * R64;
    const float dec = __ldg(decay_p);
    const float* xg0 = ode + (size_t)row0 * T_LEN;

    Chain c0 = {0.0f, 0, 0, 0, 0, 0};         // row lane
    Chain c1 = {0.0f, 0, 0, 0, 0, 0};         // row lane+32

    if (wid == 1) {
        cp_chunk_issue(xg0 + 0 * TC, xt + 0 * R64 * STRW, q2, m2); cp_commit();
        cp_chunk_issue(xg0 + 1 * TC, xt + 1 * R64 * STRW, q2, m2); cp_commit();
        asm volatile("cp.async.wait_group 1;\n" ::: "memory");  // chunk 0 ready
    }
    __syncthreads();

    for (int k = 0; k < NCH + 3; ++k) {
        // ---------------- w0: scan chunk k, 2 independent chains ----------------
        if (wid == 0 && k < NCH) {
            const float* xr0 = xt + (k % XD) * R64 * STRW + lane * STRW;
            const float* xr1 = xr0 + 32 * STRW;
            float* vr0 = vb + (k % VD) * R64 * STRW + lane * STRW;
            float* vr1 = vr0 + 32 * STRW;
            float* sr0 = ssb + (k % VD) * R64 * STRW + lane * STRW;
            float* sr1 = sr0 + 32 * STRW;
            unsigned b0_0 = 0u, b1_0 = 0u, b0_1 = 0u, b1_1 = 0u;
            if (k == 0) {
                general_chunk(c0, xr0, vr0, sr0, b0_0, b1_0, dec);
                general_chunk(c1, xr1, vr1, sr1, b0_1, b1_1, dec);
            } else {
                float4 xc0 = *reinterpret_cast<const float4*>(xr0);
                float4 xc1 = *reinterpret_cast<const float4*>(xr1);
#pragma unroll
                for (int g4 = 0; g4 < 16; ++g4) {
                    float4 xn0, xn1;
                    if (g4 < 15) {
                        xn0 = *reinterpret_cast<const float4*>(xr0 + 4 * (g4 + 1));
                        xn1 = *reinterpret_cast<const float4*>(xr1 + 4 * (g4 + 1));
                    }
                    // compile-time word select (g4 constant after unroll)
                    unsigned& w0 = (g4 < 8) ? b0_0 : b1_0;
                    unsigned& w1 = (g4 < 8) ? b0_1 : b1_1;
                    const unsigned p0 = 1u << ((4 * g4)     & 31);
                    const unsigned p1 = 1u << ((4 * g4 + 1) & 31);
                    const unsigned p2 = 1u << ((4 * g4 + 2) & 31);
                    const unsigned p3 = 1u << ((4 * g4 + 3) & 31);
                    float4 v40, v41, sf0, sf1;
                    v40.x = lif_step(c0, xc0.x, dec, sf0.x, w0, p0);
                    v41.x = lif_step(c1, xc1.x, dec, sf1.x, w1, p0);
                    v40.y = lif_step(c0, xc0.y, dec, sf0.y, w0, p1);
                    v41.y = lif_step(c1, xc1.y, dec, sf1.y, w1, p1);
                    v40.z = lif_step(c0, xc0.z, dec, sf0.z, w0, p2);
                    v41.z = lif_step(c1, xc1.z, dec, sf1.z, w1, p2);
                    v40.w = lif_step(c0, xc0.w, dec, sf0.w, w0, p3);
                    v41.w = lif_step(c1, xc1.w, dec, sf1.w, w1, p3);
                    *reinterpret_cast<float4*>(vr0 + 4 * g4) = v40;
                    *reinterpret_cast<float4*>(vr1 + 4 * g4) = v41;
                    *reinterpret_cast<float4*>(sr0 + 4 * g4) = sf0;
                    *reinterpret_cast<float4*>(sr1 + 4 * g4) = sf1;
                    xc0 = xn0; xc1 = xn1;
                }
            }
            unsigned* sbw = sb + (k % SD) * R64 * 2;
            sbw[lane * 2 + 0] = b0_0;
            sbw[lane * 2 + 1] = b1_0;
            sbw[(lane + 32) * 2 + 0] = b0_1;
            sbw[(lane + 32) * 2 + 1] = b1_1;
        }

        // ------ w1: prefetch + coalesced v store (chunk k-1) ------
        if (wid == 1) {
            if (k + 2 < NCH)
                cp_chunk_issue(xg0 + (size_t)(k + 2) * TC,
                               xt + ((k + 2) % XD) * R64 * STRW, q2, m2);
            cp_commit();   // ALWAYS commit (empty on tail): wait_group depth
                           // stays exact so chunk k+1 is provably complete
            const int c = k - 1;
            if (c >= 0 && c < NCH) {
                const float* vbb = vb + (c % VD) * R64 * STRW;
                float* vout = v_out + (size_t)row0 * T_LEN + (size_t)c * TC;
#pragma unroll 4
                for (int r = 0; r < 32; ++r) {
                    const int rr = 2 * r + q2;
                    float4 v4 = *reinterpret_cast<const float4*>(vbb + rr * STRW + 4 * m2);
                    *reinterpret_cast<float4*>(vout + (size_t)rr * T_LEN + 4 * m2) = v4;
                }
            }
            asm volatile("cp.async.wait_group 1;\n" ::: "memory");
        }

        // ------ w2: s copy (k-1) + dv window masks (k-2) + dv share (k-3) ------
        if (wid == 2) {
            const int c = k - 1;
            if (c >= 0 && c < NCH) {
                const float* sbbuf = ssb + (c % VD) * R64 * STRW;
                float* sout = s_out + (size_t)row0 * T_LEN + (size_t)c * TC;
#pragma unroll 4
                for (int r = 0; r < 32; ++r) {
                    const int rr = 2 * r + q2;
                    float4 s4v = *reinterpret_cast<const float4*>(sbbuf + rr * STRW + 4 * m2);
                    *reinterpret_cast<float4*>(sout + (size_t)rr * T_LEN + 4 * m2) = s4v;
                }
            }
            const int ca = k - 2;
            if (ca >= 0 && ca < NCH) {
                unsigned* Wdst = Wr + (k & 1) * R64 * 2;
#pragma unroll
                for (int cc = 0; cc < 2; ++cc) {
                    const int rw = lane + 32 * cc;
                    const unsigned* sbc = sb + (ca % SD) * R64 * 2 + rw * 2;
#pragma unroll
                    for (int h = 0; h < 2; ++h) {
                        unsigned mm, mp, mn;
                        if (h == 0) {
                            mm = sbc[0];
                            mp = (ca > 0) ? sb[((ca - 1) % SD) * R64 * 2 + rw * 2 + 1] : 0u;
                            mn = sbc[1] & 1u;
                            if (ca == 0) mm &= ~1u;  // spike at t=0 zeroes nothing
                        } else {
                            mm = sbc[1];
                            mp = sbc[0];
                            if (ca == 0) mp &= ~1u;
                            mn = (ca + 1 < NCH)
                                 ? (sb[((ca + 1) % SD) * R64 * 2 + rw * 2 + 0] & 1u) : 0u;
                        }
                        unsigned long long W = ((unsigned long long)mm << 5) | (mp >> 27)
                                             | ((unsigned long long)mn << 37);
                        W |= W >> 1; W |= W >> 2; W |= W >> 3;
                        Wdst[rw * 2 + h] = (unsigned)W;
                    }
                }
            }
            const int cd = k - 3;
            if (cd >= 0 && cd < NCH) {
                dv_store_rows(xt + (cd % XD) * R64 * STRW,
                              Wr + ((k - 1) & 1) * R64 * 2,
                              dv_out + (size_t)row0 * T_LEN + (size_t)cd * TC,
                              0, DVSPLIT, q2, m2);
            }
        }

        // ------ w3: dv store remainder (chunk k-3) ------
        if (wid == 3) {
            const int cd = k - 3;
            if (cd >= 0 && cd < NCH) {
                dv_store_rows(xt + (cd % XD) * R64 * STRW,
                              Wr + ((k - 1) & 1) * R64 * 2,
                              dv_out + (size_t)row0 * T_LEN + (size_t)cd * TC,
                              DVSPLIT, 32, q2, m2);
            }
        }

        __syncthreads();
    }
}

extern "C" void kernel_launch(void* const* d_in, const int* in_sizes, int n_in,
                              void* d_out, int out_size)
{
    const float* ode     = (const float*)d_in[0];
    const float* decay_p = (const float*)d_in[1];
    float*       out     = (float*)d_out;

    const int BT = in_sizes[0];
    const int B  = BT / T_LEN;

    float* v_out  = out;
    float* s_out  = out + (size_t)BT;
    float* dv_out = out + (size_t)2 * BT;

    cudaFuncSetAttribute(lif_fused, cudaFuncAttributeMaxDynamicSharedMemorySize,
                         (int)SMEM_BYTES);
    lif_fused<<<B / R64, 128, SMEM_BYTES>>>(ode, decay_p, v_out, s_out, dv_out);
}